// round 7
// baseline (speedup 1.0000x reference)
#include <cuda_runtime.h>
#include <cuda_fp16.h>
#include <math.h>
#include <stdint.h>

// ---------------- problem constants ----------------
#define HDIM  1024
#define BSZ   4096
#define TLEN  128
#define K2    2048            // stored K layout: [h_hi | h_lo] (fp16)
#define NGATE 4096            // 4 gates x HDIM, interleaved n' = j*4 + g
#define MT    256             // M per cluster
#define NT    256             // N per tile
#define NCHUNK 32             // K chunks of 32 elems (64B rows, SW64)
#define NSTAGE 4
#define JT2   32              // partial slots: 16 n-tiles x 2 nc-groups
#define NTHREADS 288          // w0 mma, w1-4 producers(+epi B), w5-8 epi A

#if defined(__CUDA_ARCH__) && (defined(__CUDA_ARCH_FEAT_SM103_ALL) || defined(__CUDA_ARCH_FEAT_SM100_ALL) || defined(__CUDA_ARCH_FEAT_SM101_ALL))
#define HAS_TCGEN05 1
#else
#define HAS_TCGEN05 0
#endif

// ---------------- persistent device state ----------------
__device__ __half g_A[2][(size_t)BSZ * K2];       // activations [h_hi|h_lo] (ping-pong)
__device__ __half g_Bp[(size_t)NGATE * HDIM];     // weights fp16, gate-interleaved rows
__device__ float g_c[(size_t)BSZ * HDIM];
__device__ float g_biasp[NGATE];
__device__ float g_wihp[NGATE];
__device__ float g_woutp[HDIM];
__device__ float g_partial[2][(size_t)BSZ * JT2]; // double-buffered

// ---------------- smem layout ----------------
#define SM_TMEM   0
#define SM_FULL0  64                  // 4 x 8B (used on rank 0)
#define SM_EMPTY0 (SM_FULL0 + 8*NSTAGE)
#define SM_DONE   (SM_EMPTY0 + 8*NSTAGE)
#define SM_STAGE  1024
#define STAGE_BYTES 32768             // A_hi 8K | A_lo 8K | B0 8K | B1 8K (per CTA)
#define OFF_AHI 0
#define OFF_ALO 8192
#define OFF_B0  16384
#define OFF_B1  24576
#define DSMEM (SM_STAGE + NSTAGE*STAGE_BYTES)

// idesc cg2: F32 accum, F16 a/b, N=256 (32<<17), M=256 (16<<24)
#define IDESC_CG2 0x10400010u

// ---------------- arch-neutral helpers ----------------
__device__ __forceinline__ uint32_t smem_u32(const void* p) {
    uint32_t a;
    asm("{ .reg .u64 t; cvta.to.shared.u64 t, %1; cvt.u32.u64 %0, t; }" : "=r"(a) : "l"(p));
    return a;
}
__device__ __forceinline__ uint32_t elect1() {
    uint32_t r;
    asm volatile("{ .reg .pred p; elect.sync _|p, 0xFFFFFFFF; selp.b32 %0, 1, 0, p; }" : "=r"(r));
    return r;
}
__device__ __forceinline__ uint32_t ctarank() {
    uint32_t r;
    asm("mov.u32 %0, %%cluster_ctarank;" : "=r"(r));
    return r;
}
#define CLUSTER_SYNC() do { \
    asm volatile("barrier.cluster.arrive.aligned;" ::: "memory"); \
    asm volatile("barrier.cluster.wait.aligned;" ::: "memory"); } while (0)
#define MBARRIER_INIT(addr, cnt) \
    asm volatile("mbarrier.init.shared.b64 [%0], %1;" :: "r"((uint32_t)(addr)), "r"((uint32_t)(cnt)) : "memory")
#define MBARRIER_WAIT_PARITY(addr, par) do { \
    uint32_t _m = (uint32_t)(addr); uint32_t _p = (uint32_t)(par); uint32_t _d; \
    asm volatile("{ .reg .pred p; mbarrier.try_wait.parity.acquire.cta.shared::cta.b64 p, [%1], %2; selp.b32 %0,1,0,p; }" \
        : "=r"(_d) : "r"(_m), "r"(_p) : "memory"); \
    if (!_d) { \
        asm volatile("{ .reg .pred P1; WL_%=: mbarrier.try_wait.parity.acquire.cta.shared::cta.b64 P1, [%0], %1, 0x989680; @P1 bra.uni WD_%=; bra.uni WL_%=; WD_%=: }" \
            :: "r"(_m), "r"(_p) : "memory"); \
    } } while (0)
#define MBARRIER_WAIT_PARITY_CLU(addr, par) do { \
    uint32_t _m = (uint32_t)(addr); uint32_t _p = (uint32_t)(par); uint32_t _d; \
    asm volatile("{ .reg .pred p; mbarrier.try_wait.parity.acquire.cluster.shared::cta.b64 p, [%1], %2; selp.b32 %0,1,0,p; }" \
        : "=r"(_d) : "r"(_m), "r"(_p) : "memory"); \
    if (!_d) { \
        asm volatile("{ .reg .pred P1; WL_%=: mbarrier.try_wait.parity.acquire.cluster.shared::cta.b64 P1, [%0], %1, 0x989680; @P1 bra.uni WD_%=; bra.uni WL_%=; WD_%=: }" \
            :: "r"(_m), "r"(_p) : "memory"); \
    } } while (0)
// arrive on rank-0 CTA's barrier (works from either rank)
#define ARRIVE_FULL_RANK0(addr) \
    asm volatile("{ .reg .b32 ra; mapa.shared::cluster.u32 ra, %0, 0; " \
                 "mbarrier.arrive.release.cluster.shared::cluster.b64 _, [ra]; }" \
                 :: "r"((uint32_t)(addr)) : "memory")
__device__ __forceinline__ void cp16(uint32_t saddr, const void* gaddr) {
    asm volatile("cp.async.cg.shared.global [%0], [%1], 16;" :: "r"(saddr), "l"(gaddr));
}
#define CP_COMMIT() asm volatile("cp.async.commit_group;" ::: "memory")
#define CP_WAIT_GROUP(n) asm volatile("cp.async.wait_group %0;" :: "n"(n) : "memory")
__device__ __forceinline__ uint32_t swz64(uint32_t o) { return o ^ ((o >> 3) & 0x30); }

// SW64 K-major smem descriptor: layout 4, version 1, SBO=32, LBO=1
static __device__ __forceinline__ uint64_t make_desc_sw64(uint32_t addr) {
    const uint64_t base = (uint64_t(4) << 61) | (uint64_t(1) << 46) | (uint64_t(32) << 32) | (uint64_t(1) << 16);
    return base | ((uint64_t)(addr >> 4) & 0x3FFF);
}

// ---------------- tcgen05 (sm_103a-only PTX pass) ----------------
#if HAS_TCGEN05
#define TCGEN05_ALLOC_CG2(sa, n) \
    asm volatile("tcgen05.alloc.cta_group::2.sync.aligned.shared::cta.b32 [%0], %1;" :: "r"((uint32_t)(sa)), "r"((uint32_t)(n)) : "memory")
#define TCGEN05_DEALLOC_CG2(t, n) \
    asm volatile("tcgen05.dealloc.cta_group::2.sync.aligned.b32 %0, %1;" :: "r"(t), "r"((uint32_t)(n)))
#define TCGEN05_RELINQUISH_CG2() \
    asm volatile("tcgen05.relinquish_alloc_permit.cta_group::2.sync.aligned;")
#define TCGEN05_COMMIT_MC(mb) \
    asm volatile("tcgen05.commit.cta_group::2.mbarrier::arrive::one.shared::cluster.multicast::cluster.b64 [%0], %1;" \
        :: "r"((uint32_t)(mb)), "h"((uint16_t)0x3) : "memory")
#define TCGEN05_FENCE_AFTER()  asm volatile("tcgen05.fence::after_thread_sync;" ::: "memory")
#define TCGEN05_WAIT_LD()      asm volatile("tcgen05.wait::ld.sync.aligned;" ::: "memory")
#define FENCE_PROXY_ASYNC()    asm volatile("fence.proxy.async.shared::cta;" ::: "memory")

#define TCGEN05_LD_X32(r, ta) \
    asm volatile("tcgen05.ld.sync.aligned.32x32b.x32.b32 " \
        "{%0,%1,%2,%3,%4,%5,%6,%7,%8,%9,%10,%11,%12,%13,%14,%15," \
        "%16,%17,%18,%19,%20,%21,%22,%23,%24,%25,%26,%27,%28,%29,%30,%31}, [%32];" \
        : "=r"((r)[0]),"=r"((r)[1]),"=r"((r)[2]),"=r"((r)[3]),"=r"((r)[4]),"=r"((r)[5]),"=r"((r)[6]),"=r"((r)[7]), \
          "=r"((r)[8]),"=r"((r)[9]),"=r"((r)[10]),"=r"((r)[11]),"=r"((r)[12]),"=r"((r)[13]),"=r"((r)[14]),"=r"((r)[15]), \
          "=r"((r)[16]),"=r"((r)[17]),"=r"((r)[18]),"=r"((r)[19]),"=r"((r)[20]),"=r"((r)[21]),"=r"((r)[22]),"=r"((r)[23]), \
          "=r"((r)[24]),"=r"((r)[25]),"=r"((r)[26]),"=r"((r)[27]),"=r"((r)[28]),"=r"((r)[29]),"=r"((r)[30]),"=r"((r)[31]) \
        : "r"(ta))

__device__ __forceinline__ void mma_f16_ss_cg2(uint32_t d, uint64_t ad, uint64_t bd, uint32_t en) {
    asm volatile(
        "{ .reg .pred p; setp.ne.u32 p, %4, 0;\n\t"
        "tcgen05.mma.cta_group::2.kind::f16 [%0], %1, %2, %3, {%5,%5,%5,%5,%5,%5,%5,%5}, p; }"
        :: "r"(d), "l"(ad), "l"(bd), "r"(IDESC_CG2), "r"(en), "r"(0u) : "memory");
}
#endif

// ---------------- prep kernels ----------------
__global__ void prep_weights(const float* __restrict__ W_ih, const float* __restrict__ W_hh,
                             const float* __restrict__ b_ih, const float* __restrict__ b_hh,
                             const float* __restrict__ W_out,
                             __half* __restrict__ Bp, float* __restrict__ biasp,
                             float* __restrict__ wihp, float* __restrict__ woutp)
{
    int idx = blockIdx.x * blockDim.x + threadIdx.x;
    if (idx >= NGATE * HDIM) return;
    int np = idx / HDIM, k = idx - np * HDIM;
    int gg = np & 3, j = np >> 2;
    int src = gg * HDIM + j;
    Bp[(size_t)np * HDIM + k] = __float2half_rn(W_hh[(size_t)src * HDIM + k]);
    if (k == 0) { biasp[np] = b_ih[src] + b_hh[src]; wihp[np] = W_ih[src]; }
    if (np == 0) woutp[k] = W_out[k];
}

__global__ void prep_state(const float* __restrict__ hidden, const float* __restrict__ cell,
                           __half* __restrict__ A0, float* __restrict__ cbuf)
{
    int idx = blockIdx.x * blockDim.x + threadIdx.x;
    if (idx >= BSZ * HDIM) return;
    int m = idx / HDIM, k = idx - m * HDIM;
    float h = hidden[idx];
    __half hi = __float2half_rn(h);
    __half lo = __float2half_rn(h - __half2float(hi));
    A0[(size_t)m * K2 + k]        = hi;
    A0[(size_t)m * K2 + 1024 + k] = lo;
    cbuf[idx] = cell[idx];
}

#if HAS_TCGEN05
// LSTM pointwise epilogue for one 32-col TMEM chunk, one row m.
__device__ __forceinline__ float epi_chunk(
    uint32_t tmem_addr, int nbase, int jb, float xb,
    float* __restrict__ cbuf, __half* __restrict__ Aout,
    const float* __restrict__ biasp, const float* __restrict__ wihp,
    const float* __restrict__ woutp, size_t mrow, size_t arow)
{
    uint32_t r[32];
    TCGEN05_LD_X32(r, tmem_addr);
    TCGEN05_WAIT_LD();
    const float4 ca  = *(const float4*)(cbuf + mrow + jb);
    const float4 cb2 = *(const float4*)(cbuf + mrow + jb + 4);
    float cold[8] = {ca.x, ca.y, ca.z, ca.w, cb2.x, cb2.y, cb2.z, cb2.w};
    float cn[8];
    union { __half h[8]; uint4 v; } Uhi, Ulo;
    float psum = 0.0f;
#pragma unroll
    for (int jl = 0; jl < 8; jl++) {
        const int nn = nbase + jl * 4;
        float iv = __uint_as_float(r[jl * 4 + 0]) + biasp[nn + 0] + xb * wihp[nn + 0];
        float fv = __uint_as_float(r[jl * 4 + 1]) + biasp[nn + 1] + xb * wihp[nn + 1];
        float gv = __uint_as_float(r[jl * 4 + 2]) + biasp[nn + 2] + xb * wihp[nn + 2];
        float ov = __uint_as_float(r[jl * 4 + 3]) + biasp[nn + 3] + xb * wihp[nn + 3];
        const float si = __fdividef(1.0f, 1.0f + __expf(-iv));
        const float sf = __fdividef(1.0f, 1.0f + __expf(-fv));
        const float so2 = __fdividef(1.0f, 1.0f + __expf(-ov));
        const float tg = 1.0f - __fdividef(2.0f, __expf(2.0f * gv) + 1.0f);
        const float c2 = sf * cold[jl] + si * tg;
        const float tc = 1.0f - __fdividef(2.0f, __expf(2.0f * c2) + 1.0f);
        const float hn = so2 * tc;
        cn[jl] = c2;
        const __half hi = __float2half_rn(hn);
        Uhi.h[jl] = hi;
        Ulo.h[jl] = __float2half_rn(hn - __half2float(hi));
        psum = fmaf(hn, woutp[jb + jl], psum);
    }
    *(float4*)(cbuf + mrow + jb)     = make_float4(cn[0], cn[1], cn[2], cn[3]);
    *(float4*)(cbuf + mrow + jb + 4) = make_float4(cn[4], cn[5], cn[6], cn[7]);
    *(uint4*)(Aout + arow + jb)        = Uhi.v;
    *(uint4*)(Aout + arow + 1024 + jb) = Ulo.v;
    return psum;
}
#endif

// ---------------- cg2 fused LSTM step ----------------
__global__ void __launch_bounds__(NTHREADS, 1)
lstm_step_cg2(const __half* __restrict__ Ain, __half* __restrict__ Aout,
              const __half* __restrict__ Bp, float* __restrict__ cbuf,
              const float* __restrict__ biasp, const float* __restrict__ wihp,
              const float* __restrict__ woutp,
              const float* __restrict__ partial_prev, float* __restrict__ partial,
              const float* __restrict__ b_out, float* __restrict__ out,
              int t, int use_x)
{
#if HAS_TCGEN05
    extern __shared__ char smem[];
    const uint32_t sbase = smem_u32(smem);
    const int tid = threadIdx.x, wid = tid >> 5, lid = tid & 31;
    const uint32_t rank = ctarank();
    const int cid = blockIdx.x >> 1;
    const int mx = cid & 15, nyg = cid >> 4;       // 16 m-bands x 8 n-groups
    const int m0 = mx * MT;

    if (tid == 0) {
#pragma unroll
        for (int s = 0; s < NSTAGE; s++) {
            MBARRIER_INIT(sbase + SM_FULL0 + 8 * s, 8);   // 4 warps x 2 CTAs
            MBARRIER_INIT(sbase + SM_EMPTY0 + 8 * s, 1);
        }
        MBARRIER_INIT(sbase + SM_DONE, 1);
    }
    if (wid == 0) TCGEN05_ALLOC_CG2(sbase + SM_TMEM, 512);
    __syncthreads();
    uint32_t tmem;
    asm volatile("ld.shared.b32 %0, [%1];" : "=r"(tmem) : "r"(sbase + SM_TMEM));
    CLUSTER_SYNC();   // peer mbarriers initialized before any remote arrive / commit

    if (wid == 0) {
        // ================= MMA warp (leader rank 0 issues) =================
        if (rank == 0) {
            uint64_t dAhi[NSTAGE], dAlo[NSTAGE], dB0[NSTAGE], dB1[NSTAGE];
#pragma unroll
            for (int s = 0; s < NSTAGE; s++) {
                const uint32_t aT = sbase + SM_STAGE + s * STAGE_BYTES;
                dAhi[s] = make_desc_sw64(aT + OFF_AHI);
                dAlo[s] = make_desc_sw64(aT + OFF_ALO);
                dB0[s]  = make_desc_sw64(aT + OFF_B0);
                dB1[s]  = make_desc_sw64(aT + OFF_B1);
            }
            for (int c = 0; c < NCHUNK; c++) {
                const int s = c & 3;
                const int par = (c >> 2) & 1;
                MBARRIER_WAIT_PARITY_CLU(sbase + SM_FULL0 + 8 * s, par);
                FENCE_PROXY_ASYNC();
                if (elect1()) {
#pragma unroll
                    for (int kk = 0; kk < 2; kk++) {
                        const uint32_t en0 = (c == 0 && kk == 0) ? 0u : 1u;
                        mma_f16_ss_cg2(tmem + 0,   dAhi[s] + kk * 2, dB0[s] + kk * 2, en0);
                        mma_f16_ss_cg2(tmem + 0,   dAlo[s] + kk * 2, dB0[s] + kk * 2, 1u);
                        mma_f16_ss_cg2(tmem + 256, dAhi[s] + kk * 2, dB1[s] + kk * 2, en0);
                        mma_f16_ss_cg2(tmem + 256, dAlo[s] + kk * 2, dB1[s] + kk * 2, 1u);
                    }
                    TCGEN05_COMMIT_MC(sbase + SM_EMPTY0 + 8 * s);
                }
            }
            if (elect1()) TCGEN05_COMMIT_MC(sbase + SM_DONE);
        }
    } else {
        // ================= producers (w1-4) + epilogue =================
        const int g = (wid <= 4) ? 1 : 0;             // nc-group: prod warps take 4-7
        const int lane_row = (wid & 3) * 32 + lid;    // lanes 0..127 per group
        const int m = m0 + (int)rank * 128 + lane_row;

        float xb = 0.0f;
        if (g == 0) {
            // epi-A warps: compute feedback early, hidden under MMA phase
            if (use_x) {
                float s = b_out[0];
                const float4* pp = (const float4*)(partial_prev + (size_t)m * JT2);
#pragma unroll
                for (int i = 0; i < 8; i++) {
                    float4 p = pp[i];
                    s += p.x + p.y + p.z + p.w;
                }
                xb = s;
                if (nyg == 0) out[(size_t)m * TLEN + (t - 1)] = s;
            }
        } else {
            // -------- producer streaming --------
            const int pid = tid - 32;             // 0..127
            const int r0 = pid >> 2;              // 0..31
            const int c16 = pid & 3;
            uint32_t so[4];
#pragma unroll
            for (int u = 0; u < 4; u++) so[u] = swz64((r0 + 32 * u) * 64 + c16 * 16);
            const char* gAh = (const char*)Ain + (size_t)(m0 + rank * 128 + r0) * (K2 * 2) + c16 * 16;
            const char* gAl = gAh + 2048;
            const char* gB0 = (const char*)Bp + (size_t)(nyg * NT + rank * 128 + r0) * (HDIM * 2) + c16 * 16;
            const char* gB1 = (const char*)Bp + (size_t)((nyg + 8) * NT + rank * 128 + r0) * (HDIM * 2) + c16 * 16;

            for (int c = 0; c < NCHUNK; c++) {
                const int s = c & 3;
                const int par = ((c >> 2) & 1) ^ 1;
                MBARRIER_WAIT_PARITY(sbase + SM_EMPTY0 + 8 * s, par);
                const uint32_t sT = sbase + SM_STAGE + s * STAGE_BYTES;
                const size_t koff = (size_t)c * 64;
#pragma unroll
                for (int u = 0; u < 4; u++) {
                    const size_t growA = (size_t)u * 32 * (K2 * 2);
                    const size_t growB = (size_t)u * 32 * (HDIM * 2);
                    cp16(sT + OFF_AHI + so[u], gAh + growA + koff);
                    cp16(sT + OFF_ALO + so[u], gAl + growA + koff);
                    cp16(sT + OFF_B0  + so[u], gB0 + growB + koff);
                    cp16(sT + OFF_B1  + so[u], gB1 + growB + koff);
                }
                CP_COMMIT();
                if (c >= 2) {
                    CP_WAIT_GROUP(2);
                    FENCE_PROXY_ASYNC();
                    __syncwarp();
                    if (elect1()) ARRIVE_FULL_RANK0(sbase + SM_FULL0 + 8 * ((c - 2) & 3));
                }
            }
            CP_WAIT_GROUP(0);
            FENCE_PROXY_ASYNC();
            __syncwarp();
            if (elect1()) {
                ARRIVE_FULL_RANK0(sbase + SM_FULL0 + 8 * ((NCHUNK - 2) & 3));
                ARRIVE_FULL_RANK0(sbase + SM_FULL0 + 8 * ((NCHUNK - 1) & 3));
            }
            // feedback for the epilogue columns this group handles
            if (use_x) {
                float s = b_out[0];
                const float4* pp = (const float4*)(partial_prev + (size_t)m * JT2);
#pragma unroll
                for (int i = 0; i < 8; i++) {
                    float4 p = pp[i];
                    s += p.x + p.y + p.z + p.w;
                }
                xb = s;
            }
        }

        // -------- epilogue: this CTA's 128 rows, both tiles, nc-group g --------
        MBARRIER_WAIT_PARITY(sbase + SM_DONE, 0);
        TCGEN05_FENCE_AFTER();
        const size_t mrow = (size_t)m * HDIM;
        const size_t arow = (size_t)m * K2;
#pragma unroll 1
        for (int nt = 0; nt < 2; nt++) {
            const int ntg = nyg + nt * 8;
            const int n0t = ntg * NT;
            const int j0t = n0t >> 2;
            float psum = 0.0f;
#pragma unroll 1
            for (int ncl = 0; ncl < 4; ncl++) {
                const int nc = g * 4 + ncl;
                psum += epi_chunk(tmem + nt * 256 + nc * 32,
                                  n0t + nc * 32, j0t + nc * 8, xb,
                                  cbuf, Aout, biasp, wihp, woutp, mrow, arow);
            }
            partial[(size_t)m * JT2 + ntg * 2 + g] = psum;
        }
    }

    __syncthreads();
    CLUSTER_SYNC();
    if (wid == 0) {
        TCGEN05_RELINQUISH_CG2();
        TCGEN05_DEALLOC_CG2(tmem, 512);
    }
    CLUSTER_SYNC();
#endif
}

// final column (t = TLEN-1) reduce
__global__ void pred_final(const float* __restrict__ partial, const float* __restrict__ b_out,
                           float* __restrict__ out)
{
    const int b = blockIdx.x * blockDim.x + threadIdx.x;
    if (b < BSZ) {
        float s = b_out[0];
        const float* p = partial + (size_t)b * JT2;
#pragma unroll
        for (int i = 0; i < JT2; i++) s += p[i];
        out[(size_t)b * TLEN + (TLEN - 1)] = s;
    }
}

// ---------------- launch ----------------
extern "C" void kernel_launch(void* const* d_in, const int* in_sizes, int n_in,
                              void* d_out, int out_size)
{
    const float* hidden = (const float*)d_in[0];
    const float* cell   = (const float*)d_in[1];
    const float* W_ih   = (const float*)d_in[2];
    const float* W_hh   = (const float*)d_in[3];
    const float* b_ih   = (const float*)d_in[4];
    const float* b_hh   = (const float*)d_in[5];
    const float* W_out  = (const float*)d_in[6];
    const float* b_out  = (const float*)d_in[7];
    float* out = (float*)d_out;

    __half *Abuf, *Bp;
    float *cbuf, *biasp, *wihp, *woutp, *part;
    cudaGetSymbolAddress((void**)&Abuf,  g_A);
    cudaGetSymbolAddress((void**)&Bp,    g_Bp);
    cudaGetSymbolAddress((void**)&cbuf,  g_c);
    cudaGetSymbolAddress((void**)&biasp, g_biasp);
    cudaGetSymbolAddress((void**)&wihp,  g_wihp);
    cudaGetSymbolAddress((void**)&woutp, g_woutp);
    cudaGetSymbolAddress((void**)&part,  g_partial);

    cudaFuncSetAttribute(lstm_step_cg2, cudaFuncAttributeMaxDynamicSharedMemorySize, DSMEM);

    prep_weights<<<(NGATE * HDIM + 255) / 256, 256>>>(W_ih, W_hh, b_ih, b_hh, W_out,
                                                      Bp, biasp, wihp, woutp);
    prep_state<<<(BSZ * HDIM + 255) / 256, 256>>>(hidden, cell, Abuf, cbuf);

    cudaLaunchConfig_t cfg = {};
    cfg.gridDim = dim3(256, 1, 1);
    cfg.blockDim = dim3(NTHREADS, 1, 1);
    cfg.dynamicSmemBytes = DSMEM;
    cfg.stream = 0;
    cudaLaunchAttribute attrs[1];
    attrs[0].id = cudaLaunchAttributeClusterDimension;
    attrs[0].val.clusterDim = {2, 1, 1};
    cfg.attrs = attrs;
    cfg.numAttrs = 1;

    const size_t NA = (size_t)BSZ * K2;
    const size_t NP = (size_t)BSZ * JT2;
    for (int t = 0; t < TLEN; t++) {
        const __half* Ain = Abuf + (size_t)(t & 1) * NA;
        __half* Aout = Abuf + (size_t)((t + 1) & 1) * NA;
        const float* ppart = part + (size_t)((t + 1) & 1) * NP;
        float* cpart = part + (size_t)(t & 1) * NP;
        cudaLaunchKernelEx(&cfg, lstm_step_cg2, Ain, Aout, Bp, cbuf, biasp, wihp, woutp,
                           ppart, cpart, b_out, out, t, (t > 0) ? 1 : 0);
    }
    pred_final<<<BSZ / 256, 256>>>(part + (size_t)((TLEN - 1) & 1) * NP, b_out, out);
}

// round 8
// speedup vs baseline: 1.5182x; 1.5182x over previous
#include <cuda_runtime.h>
#include <cuda.h>
#include <cuda_fp16.h>
#include <math.h>
#include <stdint.h>

// ---------------- problem constants ----------------
#define HDIM  1024
#define BSZ   4096
#define TLEN  128
#define K2    2048            // stored K layout: [h_hi | h_lo] (fp16)
#define NGATE 4096            // 4 gates x HDIM, interleaved n' = j*4 + g
#define MT    256
#define NT    256
#define NCHUNK 32             // K chunks of 32 elems (64B rows, SW64)
#define NSTAGE 4
#define JT    16
#define NTHREADS 320          // w0 MMA, w1 TMA, w2-9 epilogue

#if defined(__CUDA_ARCH__) && (defined(__CUDA_ARCH_FEAT_SM103_ALL) || defined(__CUDA_ARCH_FEAT_SM100_ALL) || defined(__CUDA_ARCH_FEAT_SM101_ALL))
#define HAS_TCGEN05 1
#else
#define HAS_TCGEN05 0
#endif

// ---------------- persistent device state ----------------
__device__ __align__(1024) __half g_A[2][(size_t)BSZ * K2];   // [h_hi|h_lo] ping-pong
__device__ __align__(1024) __half g_Bp[(size_t)NGATE * HDIM]; // weights fp16, gate-interleaved
__device__ float g_c[(size_t)BSZ * HDIM];
__device__ float g_biasp[NGATE];
__device__ float g_wihp[NGATE];
__device__ float g_woutp[HDIM];
__device__ float g_partial[2][(size_t)BSZ * JT];              // double-buffered

// ---------------- smem layout ----------------
#define SM_TMEM   0
#define SM_FULL0  64
#define SM_EMPTY0 (SM_FULL0 + 8*NSTAGE)
#define SM_DONE   (SM_EMPTY0 + 8*NSTAGE)
#define SM_STAGE  1024
#define STAGE_BYTES 49152       // A_hi 16K | A_lo 16K | B 16K
#define OFF_AHI 0
#define OFF_ALO 16384
#define OFF_B   32768
#define DSMEM (SM_STAGE + NSTAGE*STAGE_BYTES)

// idesc: F32 accum, F16 a/b, N=256, M=128
#define MMA_IDESC 0x08400010u

// ---------------- arch-neutral helpers ----------------
__device__ __forceinline__ uint32_t smem_u32(const void* p) {
    uint32_t a;
    asm("{ .reg .u64 t; cvta.to.shared.u64 t, %1; cvt.u32.u64 %0, t; }" : "=r"(a) : "l"(p));
    return a;
}
__device__ __forceinline__ uint32_t elect1() {
    uint32_t r;
    asm volatile("{ .reg .pred p; elect.sync _|p, 0xFFFFFFFF; selp.b32 %0, 1, 0, p; }" : "=r"(r));
    return r;
}
#define MBARRIER_INIT(addr, cnt) \
    asm volatile("mbarrier.init.shared.b64 [%0], %1;" :: "r"((uint32_t)(addr)), "r"((uint32_t)(cnt)) : "memory")
#define MBARRIER_EXPECT_TX(addr, bytes) \
    asm volatile("mbarrier.arrive.expect_tx.shared.b64 _, [%0], %1;" :: "r"((uint32_t)(addr)), "r"((uint32_t)(bytes)) : "memory")
#define MBARRIER_WAIT_PARITY(addr, par) do { \
    uint32_t _m = (uint32_t)(addr); uint32_t _p = (uint32_t)(par); uint32_t _d; \
    asm volatile("{ .reg .pred p; mbarrier.try_wait.parity.acquire.cta.shared::cta.b64 p, [%1], %2; selp.b32 %0,1,0,p; }" \
        : "=r"(_d) : "r"(_m), "r"(_p) : "memory"); \
    if (!_d) { \
        asm volatile("{ .reg .pred P1; WL_%=: mbarrier.try_wait.parity.acquire.cta.shared::cta.b64 P1, [%0], %1, 0x989680; @P1 bra.uni WD_%=; bra.uni WL_%=; WD_%=: }" \
            :: "r"(_m), "r"(_p) : "memory"); \
    } } while (0)
__device__ __forceinline__ void tma2d(uint32_t dst, const void* tmap, int x, int y, uint32_t mbar) {
    asm volatile("cp.async.bulk.tensor.2d.shared::cta.global.tile.mbarrier::complete_tx::bytes "
                 "[%0], [%1, {%2, %3}], [%4];"
                 :: "r"(dst), "l"(tmap), "r"(x), "r"(y), "r"(mbar) : "memory");
}

// SW64 K-major smem descriptor: layout 4, version 1, SBO=32, LBO=1
static __device__ __forceinline__ uint64_t make_desc_sw64(uint32_t addr) {
    const uint64_t base = (uint64_t(4) << 61) | (uint64_t(1) << 46) | (uint64_t(32) << 32) | (uint64_t(1) << 16);
    return base | ((uint64_t)(addr >> 4) & 0x3FFF);
}

// ---------------- tcgen05 (sm_103a-only PTX pass) ----------------
#if HAS_TCGEN05
#define TCGEN05_ALLOC(sa, n) \
    asm volatile("tcgen05.alloc.cta_group::1.sync.aligned.shared::cta.b32 [%0], %1;" :: "r"((uint32_t)(sa)), "r"((uint32_t)(n)) : "memory")
#define TCGEN05_DEALLOC(t, n) \
    asm volatile("tcgen05.dealloc.cta_group::1.sync.aligned.b32 %0, %1;" :: "r"(t), "r"((uint32_t)(n)))
#define TCGEN05_RELINQUISH() \
    asm volatile("tcgen05.relinquish_alloc_permit.cta_group::1.sync.aligned;")
#define TCGEN05_COMMIT(mb) \
    asm volatile("tcgen05.commit.cta_group::1.mbarrier::arrive::one.shared::cluster.b64 [%0];" :: "r"((uint32_t)(mb)) : "memory")
#define TCGEN05_FENCE_AFTER()  asm volatile("tcgen05.fence::after_thread_sync;" ::: "memory")
#define TCGEN05_WAIT_LD()      asm volatile("tcgen05.wait::ld.sync.aligned;" ::: "memory")

#define TCGEN05_LD_X32(r, ta) \
    asm volatile("tcgen05.ld.sync.aligned.32x32b.x32.b32 " \
        "{%0,%1,%2,%3,%4,%5,%6,%7,%8,%9,%10,%11,%12,%13,%14,%15," \
        "%16,%17,%18,%19,%20,%21,%22,%23,%24,%25,%26,%27,%28,%29,%30,%31}, [%32];" \
        : "=r"((r)[0]),"=r"((r)[1]),"=r"((r)[2]),"=r"((r)[3]),"=r"((r)[4]),"=r"((r)[5]),"=r"((r)[6]),"=r"((r)[7]), \
          "=r"((r)[8]),"=r"((r)[9]),"=r"((r)[10]),"=r"((r)[11]),"=r"((r)[12]),"=r"((r)[13]),"=r"((r)[14]),"=r"((r)[15]), \
          "=r"((r)[16]),"=r"((r)[17]),"=r"((r)[18]),"=r"((r)[19]),"=r"((r)[20]),"=r"((r)[21]),"=r"((r)[22]),"=r"((r)[23]), \
          "=r"((r)[24]),"=r"((r)[25]),"=r"((r)[26]),"=r"((r)[27]),"=r"((r)[28]),"=r"((r)[29]),"=r"((r)[30]),"=r"((r)[31]) \
        : "r"(ta))

__device__ __forceinline__ void mma_f16_ss(uint32_t d, uint64_t ad, uint64_t bd, uint32_t en) {
    asm volatile(
        "{ .reg .pred p; setp.ne.u32 p, %4, 0;\n\t"
        "tcgen05.mma.cta_group::1.kind::f16 [%0], %1, %2, %3, {%5,%5,%5,%5}, p; }"
        :: "r"(d), "l"(ad), "l"(bd), "r"(MMA_IDESC), "r"(en), "r"(0u) : "memory");
}
#endif

// ---------------- prep kernels ----------------
__global__ void prep_weights(const float* __restrict__ W_ih, const float* __restrict__ W_hh,
                             const float* __restrict__ b_ih, const float* __restrict__ b_hh,
                             const float* __restrict__ W_out,
                             __half* __restrict__ Bp, float* __restrict__ biasp,
                             float* __restrict__ wihp, float* __restrict__ woutp)
{
    int idx = blockIdx.x * blockDim.x + threadIdx.x;
    if (idx >= NGATE * HDIM) return;
    int np = idx / HDIM, k = idx - np * HDIM;
    int gg = np & 3, j = np >> 2;
    int src = gg * HDIM + j;
    Bp[(size_t)np * HDIM + k] = __float2half_rn(W_hh[(size_t)src * HDIM + k]);
    if (k == 0) { biasp[np] = b_ih[src] + b_hh[src]; wihp[np] = W_ih[src]; }
    if (np == 0) woutp[k] = W_out[k];
}

__global__ void prep_state(const float* __restrict__ hidden, const float* __restrict__ cell,
                           __half* __restrict__ A0, float* __restrict__ cbuf)
{
    int idx = blockIdx.x * blockDim.x + threadIdx.x;
    if (idx >= BSZ * HDIM) return;
    int m = idx / HDIM, k = idx - m * HDIM;
    float h = hidden[idx];
    __half hi = __float2half_rn(h);
    __half lo = __float2half_rn(h - __half2float(hi));
    A0[(size_t)m * K2 + k]        = hi;
    A0[(size_t)m * K2 + 1024 + k] = lo;
    cbuf[idx] = cell[idx];
}

#if HAS_TCGEN05
// LSTM pointwise for one 32-col chunk already loaded into r[32].
__device__ __forceinline__ float epi_math(
    const uint32_t* __restrict__ r, int nbase, int jb, float xb,
    float* __restrict__ cbuf, __half* __restrict__ Aout,
    const float* __restrict__ biasp, const float* __restrict__ wihp,
    const float* __restrict__ woutp, size_t mrow, size_t arow)
{
    const float4 ca  = *(const float4*)(cbuf + mrow + jb);
    const float4 cb2 = *(const float4*)(cbuf + mrow + jb + 4);
    float cold[8] = {ca.x, ca.y, ca.z, ca.w, cb2.x, cb2.y, cb2.z, cb2.w};
    float cn[8];
    union { __half h[8]; uint4 v; } Uhi, Ulo;
    float psum = 0.0f;
#pragma unroll
    for (int jl = 0; jl < 8; jl++) {
        const int nn = nbase + jl * 4;
        float iv = __uint_as_float(r[jl * 4 + 0]) + biasp[nn + 0] + xb * wihp[nn + 0];
        float fv = __uint_as_float(r[jl * 4 + 1]) + biasp[nn + 1] + xb * wihp[nn + 1];
        float gv = __uint_as_float(r[jl * 4 + 2]) + biasp[nn + 2] + xb * wihp[nn + 2];
        float ov = __uint_as_float(r[jl * 4 + 3]) + biasp[nn + 3] + xb * wihp[nn + 3];
        const float si = __fdividef(1.0f, 1.0f + __expf(-iv));
        const float sf = __fdividef(1.0f, 1.0f + __expf(-fv));
        const float so2 = __fdividef(1.0f, 1.0f + __expf(-ov));
        const float tg = 1.0f - __fdividef(2.0f, __expf(2.0f * gv) + 1.0f);
        const float c2 = sf * cold[jl] + si * tg;
        const float tc = 1.0f - __fdividef(2.0f, __expf(2.0f * c2) + 1.0f);
        const float hn = so2 * tc;
        cn[jl] = c2;
        const __half hi = __float2half_rn(hn);
        Uhi.h[jl] = hi;
        Ulo.h[jl] = __float2half_rn(hn - __half2float(hi));
        psum = fmaf(hn, woutp[jb + jl], psum);
    }
    *(float4*)(cbuf + mrow + jb)     = make_float4(cn[0], cn[1], cn[2], cn[3]);
    *(float4*)(cbuf + mrow + jb + 4) = make_float4(cn[4], cn[5], cn[6], cn[7]);
    *(uint4*)(Aout + arow + jb)        = Uhi.v;
    *(uint4*)(Aout + arow + 1024 + jb) = Ulo.v;
    return psum;
}
#endif

// ---------------- single-wave fused LSTM step (TMA + 2 tiles/CTA) ----------------
__global__ void __launch_bounds__(NTHREADS, 1)
lstm_step_tma(const __grid_constant__ CUtensorMap tmA,
              const __grid_constant__ CUtensorMap tmB,
              __half* __restrict__ Aout, float* __restrict__ cbuf,
              const float* __restrict__ biasp, const float* __restrict__ wihp,
              const float* __restrict__ woutp,
              const float* __restrict__ partial_prev, float* __restrict__ partial,
              const float* __restrict__ b_out, float* __restrict__ out,
              int t, int use_x)
{
#if HAS_TCGEN05
    extern __shared__ char smem[];
    const uint32_t sbase = smem_u32(smem);
    const int tid = threadIdx.x, wid = tid >> 5, lid = tid & 31;
    const int mx = blockIdx.x & 15, ng = blockIdx.x >> 4;   // 16 m-bands x 8 n-groups
    const int m0 = mx * MT;

    if (tid == 0) {
#pragma unroll
        for (int s = 0; s < NSTAGE; s++) {
            MBARRIER_INIT(sbase + SM_FULL0 + 8 * s, 1);
            MBARRIER_INIT(sbase + SM_EMPTY0 + 8 * s, 1);
        }
        MBARRIER_INIT(sbase + SM_DONE, 1);
    }
    if (wid == 0) TCGEN05_ALLOC(sbase + SM_TMEM, 512);
    __syncthreads();
    uint32_t tmem;
    asm volatile("ld.shared.b32 %0, [%1];" : "=r"(tmem) : "r"(sbase + SM_TMEM));

    if (wid == 0) {
        // ================= MMA warp =================
        TCGEN05_RELINQUISH();
        uint64_t dAhi[NSTAGE], dAlo[NSTAGE], dB[NSTAGE];
#pragma unroll
        for (int s = 0; s < NSTAGE; s++) {
            const uint32_t aT = sbase + SM_STAGE + s * STAGE_BYTES;
            dAhi[s] = make_desc_sw64(aT + OFF_AHI);
            dAlo[s] = make_desc_sw64(aT + OFF_ALO);
            dB[s]   = make_desc_sw64(aT + OFF_B);
        }
        for (int tile = 0; tile < 2; tile++) {
            asm volatile("bar.sync 1, 288;");          // wait epilogue TMEM drain
            for (int c = 0; c < NCHUNK; c++) {
                const int cc = tile * NCHUNK + c;
                const int s = cc & 3;
                const int par = (cc >> 2) & 1;
                MBARRIER_WAIT_PARITY(sbase + SM_FULL0 + 8 * s, par);
                if (elect1()) {
#pragma unroll
                    for (int kk = 0; kk < 2; kk++) {
                        const uint32_t en0 = (c == 0 && kk == 0) ? 0u : 1u;
                        mma_f16_ss(tmem + 0,   dAhi[s] + kk * 2,       dB[s] + kk * 2, en0);
                        mma_f16_ss(tmem + 256, dAhi[s] + 512 + kk * 2, dB[s] + kk * 2, en0);
                        mma_f16_ss(tmem + 0,   dAlo[s] + kk * 2,       dB[s] + kk * 2, 1u);
                        mma_f16_ss(tmem + 256, dAlo[s] + 512 + kk * 2, dB[s] + kk * 2, 1u);
                    }
                    TCGEN05_COMMIT(sbase + SM_EMPTY0 + 8 * s);
                }
            }
            if (elect1()) TCGEN05_COMMIT(sbase + SM_DONE);
        }
    } else if (wid == 1) {
        // ================= TMA producer warp =================
        if (elect1()) {
            for (int cc = 0; cc < 2 * NCHUNK; cc++) {
                const int s = cc & 3;
                const int par = ((cc >> 2) & 1) ^ 1;
                MBARRIER_WAIT_PARITY(sbase + SM_EMPTY0 + 8 * s, par);
                const uint32_t sT = sbase + SM_STAGE + s * STAGE_BYTES;
                const uint32_t fb = sbase + SM_FULL0 + 8 * s;
                const int c = cc & (NCHUNK - 1);
                const int n0t = (ng + (cc >> 5) * 8) * NT;
                MBARRIER_EXPECT_TX(fb, STAGE_BYTES);
                tma2d(sT + OFF_AHI, &tmA, c * 32,        m0,  fb);
                tma2d(sT + OFF_ALO, &tmA, 1024 + c * 32, m0,  fb);
                tma2d(sT + OFF_B,   &tmB, c * 32,        n0t, fb);
            }
        }
    } else {
        // ================= epilogue warps (w2-9) =================
        const int sp = wid & 3;
        const int half = (wid >= 6) ? 1 : 0;
        const int m = m0 + half * 128 + sp * 32 + lid;
        const size_t mrow = (size_t)m * HDIM;
        const size_t arow = (size_t)m * K2;

        asm volatile("bar.arrive 1, 288;");            // pre-arm drain for tile 0

        // feedback pred-reduce (overlaps tile-0 MMA)
        float xb = 0.0f;
        if (use_x) {
            float s = b_out[0];
            const float4* pp = (const float4*)(partial_prev + (size_t)m * JT);
#pragma unroll
            for (int i = 0; i < 4; i++) {
                float4 p = pp[i];
                s += p.x + p.y + p.z + p.w;
            }
            xb = s;
            if (ng == 0) out[(size_t)m * TLEN + (t - 1)] = s;
        }

        const uint32_t dbase = tmem + half * 256;
#pragma unroll 1
        for (int tile = 0; tile < 2; tile++) {
            MBARRIER_WAIT_PARITY(sbase + SM_DONE, tile);
            TCGEN05_FENCE_AFTER();
            const int nt = ng + tile * 8;
            const int n0t = nt * NT, j0t = n0t >> 2;
            float psum = 0.0f;
#pragma unroll 1
            for (int nc2 = 0; nc2 < 4; nc2++) {
                uint32_t ra[32], rb[32];
                TCGEN05_LD_X32(ra, dbase + nc2 * 64);
                TCGEN05_LD_X32(rb, dbase + nc2 * 64 + 32);
                TCGEN05_WAIT_LD();
                if (tile == 0 && nc2 == 3)
                    asm volatile("bar.arrive 1, 288;");  // release MMA for tile 1
                const int nc = nc2 * 2;
                psum += epi_math(ra, n0t + nc * 32, j0t + nc * 8, xb,
                                 cbuf, Aout, biasp, wihp, woutp, mrow, arow);
                psum += epi_math(rb, n0t + (nc + 1) * 32, j0t + (nc + 1) * 8, xb,
                                 cbuf, Aout, biasp, wihp, woutp, mrow, arow);
            }
            partial[(size_t)m * JT + nt] = psum;
        }
    }

    __syncthreads();
    if (wid == 0) TCGEN05_DEALLOC(tmem, 512);
#endif
}

// final column (t = TLEN-1) reduce
__global__ void pred_final(const float* __restrict__ partial, const float* __restrict__ b_out,
                           float* __restrict__ out)
{
    const int b = blockIdx.x * blockDim.x + threadIdx.x;
    if (b < BSZ) {
        float s = b_out[0];
        const float* p = partial + (size_t)b * JT;
#pragma unroll
        for (int i = 0; i < JT; i++) s += p[i];
        out[(size_t)b * TLEN + (TLEN - 1)] = s;
    }
}

// ---------------- launch ----------------
typedef CUresult (*PFN_tmEncode)(CUtensorMap*, CUtensorMapDataType, cuuint32_t, void*,
                                 const cuuint64_t*, const cuuint64_t*, const cuuint32_t*,
                                 const cuuint32_t*, CUtensorMapInterleave, CUtensorMapSwizzle,
                                 CUtensorMapL2promotion, CUtensorMapFloatOOBfill);

extern "C" void kernel_launch(void* const* d_in, const int* in_sizes, int n_in,
                              void* d_out, int out_size)
{
    const float* hidden = (const float*)d_in[0];
    const float* cell   = (const float*)d_in[1];
    const float* W_ih   = (const float*)d_in[2];
    const float* W_hh   = (const float*)d_in[3];
    const float* b_ih   = (const float*)d_in[4];
    const float* b_hh   = (const float*)d_in[5];
    const float* W_out  = (const float*)d_in[6];
    const float* b_out  = (const float*)d_in[7];
    float* out = (float*)d_out;

    __half *Abuf, *Bp;
    float *cbuf, *biasp, *wihp, *woutp, *part;
    cudaGetSymbolAddress((void**)&Abuf,  g_A);
    cudaGetSymbolAddress((void**)&Bp,    g_Bp);
    cudaGetSymbolAddress((void**)&cbuf,  g_c);
    cudaGetSymbolAddress((void**)&biasp, g_biasp);
    cudaGetSymbolAddress((void**)&wihp,  g_wihp);
    cudaGetSymbolAddress((void**)&woutp, g_woutp);
    cudaGetSymbolAddress((void**)&part,  g_partial);

    // tensormaps (host encode via driver entry point; no allocation)
    PFN_tmEncode tmEncode = nullptr;
    cudaDriverEntryPointQueryResult qres;
    cudaGetDriverEntryPoint("cuTensorMapEncodeTiled", (void**)&tmEncode,
                            cudaEnableDefault, &qres);
    const size_t NA = (size_t)BSZ * K2;
    CUtensorMap tmA0, tmA1, tmB;
    {
        cuuint64_t dimsA[2] = {K2, BSZ};
        cuuint64_t strA[1]  = {K2 * 2};
        cuuint32_t boxA[2]  = {32, 256};
        cuuint32_t est[2]   = {1, 1};
        tmEncode(&tmA0, CU_TENSOR_MAP_DATA_TYPE_FLOAT16, 2, (void*)Abuf,
                 dimsA, strA, boxA, est, CU_TENSOR_MAP_INTERLEAVE_NONE,
                 CU_TENSOR_MAP_SWIZZLE_64B, CU_TENSOR_MAP_L2_PROMOTION_L2_128B,
                 CU_TENSOR_MAP_FLOAT_OOB_FILL_NONE);
        tmEncode(&tmA1, CU_TENSOR_MAP_DATA_TYPE_FLOAT16, 2, (void*)(Abuf + NA),
                 dimsA, strA, boxA, est, CU_TENSOR_MAP_INTERLEAVE_NONE,
                 CU_TENSOR_MAP_SWIZZLE_64B, CU_TENSOR_MAP_L2_PROMOTION_L2_128B,
                 CU_TENSOR_MAP_FLOAT_OOB_FILL_NONE);
        cuuint64_t dimsB[2] = {HDIM, NGATE};
        cuuint64_t strB[1]  = {HDIM * 2};
        cuuint32_t boxB[2]  = {32, 256};
        tmEncode(&tmB, CU_TENSOR_MAP_DATA_TYPE_FLOAT16, 2, (void*)Bp,
                 dimsB, strB, boxB, est, CU_TENSOR_MAP_INTERLEAVE_NONE,
                 CU_TENSOR_MAP_SWIZZLE_64B, CU_TENSOR_MAP_L2_PROMOTION_L2_128B,
                 CU_TENSOR_MAP_FLOAT_OOB_FILL_NONE);
    }

    cudaFuncSetAttribute(lstm_step_tma, cudaFuncAttributeMaxDynamicSharedMemorySize, DSMEM);

    prep_weights<<<(NGATE * HDIM + 255) / 256, 256>>>(W_ih, W_hh, b_ih, b_hh, W_out,
                                                      Bp, biasp, wihp, woutp);
    prep_state<<<(BSZ * HDIM + 255) / 256, 256>>>(hidden, cell, Abuf, cbuf);

    const size_t NP = (size_t)BSZ * JT;
    for (int t = 0; t < TLEN; t++) {
        __half* Aout = Abuf + (size_t)((t + 1) & 1) * NA;
        const float* ppart = part + (size_t)((t + 1) & 1) * NP;   // (t-1)&1 == (t+1)&1
        float* cpart = part + (size_t)(t & 1) * NP;
        lstm_step_tma<<<128, NTHREADS, DSMEM>>>((t & 1) ? tmA1 : tmA0, tmB,
                                                Aout, cbuf, biasp, wihp, woutp,
                                                ppart, cpart, b_out, out,
                                                t, (t > 0) ? 1 : 0);
    }
    pred_final<<<BSZ / 256, 256>>>(part + (size_t)((TLEN - 1) & 1) * NP, b_out, out);
}

// round 9
// speedup vs baseline: 2.0145x; 1.3269x over previous
#include <cuda_runtime.h>
#include <cuda.h>
#include <cuda_fp16.h>
#include <math.h>
#include <stdint.h>

// ---------------- problem constants ----------------
#define HDIM  1024
#define BSZ   4096
#define TLEN  128
#define NGATE 4096            // 4 gates x HDIM, interleaved n' = j*4 + g
#define MT    256
#define NT    256
#define NCHUNK 32             // K chunks of 32 elems (64B rows, SW64)
#define NSTAGE 6
#define JT    16
#define NTHREADS 320          // w0 MMA, w1 TMA, w2-9 epilogue

#if defined(__CUDA_ARCH__) && (defined(__CUDA_ARCH_FEAT_SM103_ALL) || defined(__CUDA_ARCH_FEAT_SM100_ALL) || defined(__CUDA_ARCH_FEAT_SM101_ALL))
#define HAS_TCGEN05 1
#else
#define HAS_TCGEN05 0
#endif

// ---------------- persistent device state ----------------
__device__ __align__(1024) __half g_A[2][(size_t)BSZ * HDIM];  // h fp16 (ping-pong)
__device__ __align__(1024) __half g_Bp[(size_t)NGATE * HDIM];  // weights fp16, gate-interleaved
__device__ float g_c[(size_t)BSZ * HDIM];
__device__ float g_biasp[NGATE];
__device__ float g_wihp[NGATE];
__device__ float g_woutp[HDIM];
__device__ float g_partial[2][(size_t)BSZ * JT];               // double-buffered

// ---------------- smem layout ----------------
#define SM_TMEM   0
#define SM_FULL0  64
#define SM_EMPTY0 (SM_FULL0 + 8*NSTAGE)
#define SM_DONE   (SM_EMPTY0 + 8*NSTAGE)
#define SM_STAGE  1024
#define STAGE_BYTES 32768       // A 16K | B 16K
#define OFF_A 0
#define OFF_B 16384
#define DSMEM (SM_STAGE + NSTAGE*STAGE_BYTES)

// idesc: F32 accum, F16 a/b, N=256, M=128
#define MMA_IDESC 0x08400010u

// ---------------- arch-neutral helpers ----------------
__device__ __forceinline__ uint32_t smem_u32(const void* p) {
    uint32_t a;
    asm("{ .reg .u64 t; cvta.to.shared.u64 t, %1; cvt.u32.u64 %0, t; }" : "=r"(a) : "l"(p));
    return a;
}
__device__ __forceinline__ uint32_t elect1() {
    uint32_t r;
    asm volatile("{ .reg .pred p; elect.sync _|p, 0xFFFFFFFF; selp.b32 %0, 1, 0, p; }" : "=r"(r));
    return r;
}
#define MBARRIER_INIT(addr, cnt) \
    asm volatile("mbarrier.init.shared.b64 [%0], %1;" :: "r"((uint32_t)(addr)), "r"((uint32_t)(cnt)) : "memory")
#define MBARRIER_EXPECT_TX(addr, bytes) \
    asm volatile("mbarrier.arrive.expect_tx.shared.b64 _, [%0], %1;" :: "r"((uint32_t)(addr)), "r"((uint32_t)(bytes)) : "memory")
#define MBARRIER_WAIT_PARITY(addr, par) do { \
    uint32_t _m = (uint32_t)(addr); uint32_t _p = (uint32_t)(par); uint32_t _d; \
    asm volatile("{ .reg .pred p; mbarrier.try_wait.parity.acquire.cta.shared::cta.b64 p, [%1], %2; selp.b32 %0,1,0,p; }" \
        : "=r"(_d) : "r"(_m), "r"(_p) : "memory"); \
    if (!_d) { \
        asm volatile("{ .reg .pred P1; WL_%=: mbarrier.try_wait.parity.acquire.cta.shared::cta.b64 P1, [%0], %1, 0x989680; @P1 bra.uni WD_%=; bra.uni WL_%=; WD_%=: }" \
            :: "r"(_m), "r"(_p) : "memory"); \
    } } while (0)
__device__ __forceinline__ void tma2d(uint32_t dst, const void* tmap, int x, int y, uint32_t mbar) {
    asm volatile("cp.async.bulk.tensor.2d.shared::cta.global.tile.mbarrier::complete_tx::bytes "
                 "[%0], [%1, {%2, %3}], [%4];"
                 :: "r"(dst), "l"(tmap), "r"(x), "r"(y), "r"(mbar) : "memory");
}

// SW64 K-major smem descriptor: layout 4, version 1, SBO=32, LBO=1
static __device__ __forceinline__ uint64_t make_desc_sw64(uint32_t addr) {
    const uint64_t base = (uint64_t(4) << 61) | (uint64_t(1) << 46) | (uint64_t(32) << 32) | (uint64_t(1) << 16);
    return base | ((uint64_t)(addr >> 4) & 0x3FFF);
}

// ---------------- tcgen05 (sm_103a-only PTX pass) ----------------
#if HAS_TCGEN05
#define TCGEN05_ALLOC(sa, n) \
    asm volatile("tcgen05.alloc.cta_group::1.sync.aligned.shared::cta.b32 [%0], %1;" :: "r"((uint32_t)(sa)), "r"((uint32_t)(n)) : "memory")
#define TCGEN05_DEALLOC(t, n) \
    asm volatile("tcgen05.dealloc.cta_group::1.sync.aligned.b32 %0, %1;" :: "r"(t), "r"((uint32_t)(n)))
#define TCGEN05_RELINQUISH() \
    asm volatile("tcgen05.relinquish_alloc_permit.cta_group::1.sync.aligned;")
#define TCGEN05_COMMIT(mb) \
    asm volatile("tcgen05.commit.cta_group::1.mbarrier::arrive::one.shared::cluster.b64 [%0];" :: "r"((uint32_t)(mb)) : "memory")
#define TCGEN05_FENCE_AFTER()  asm volatile("tcgen05.fence::after_thread_sync;" ::: "memory")
#define TCGEN05_WAIT_LD()      asm volatile("tcgen05.wait::ld.sync.aligned;" ::: "memory")

#define TCGEN05_LD_X32(r, ta) \
    asm volatile("tcgen05.ld.sync.aligned.32x32b.x32.b32 " \
        "{%0,%1,%2,%3,%4,%5,%6,%7,%8,%9,%10,%11,%12,%13,%14,%15," \
        "%16,%17,%18,%19,%20,%21,%22,%23,%24,%25,%26,%27,%28,%29,%30,%31}, [%32];" \
        : "=r"((r)[0]),"=r"((r)[1]),"=r"((r)[2]),"=r"((r)[3]),"=r"((r)[4]),"=r"((r)[5]),"=r"((r)[6]),"=r"((r)[7]), \
          "=r"((r)[8]),"=r"((r)[9]),"=r"((r)[10]),"=r"((r)[11]),"=r"((r)[12]),"=r"((r)[13]),"=r"((r)[14]),"=r"((r)[15]), \
          "=r"((r)[16]),"=r"((r)[17]),"=r"((r)[18]),"=r"((r)[19]),"=r"((r)[20]),"=r"((r)[21]),"=r"((r)[22]),"=r"((r)[23]), \
          "=r"((r)[24]),"=r"((r)[25]),"=r"((r)[26]),"=r"((r)[27]),"=r"((r)[28]),"=r"((r)[29]),"=r"((r)[30]),"=r"((r)[31]) \
        : "r"(ta))

__device__ __forceinline__ void mma_f16_ss(uint32_t d, uint64_t ad, uint64_t bd, uint32_t en) {
    asm volatile(
        "{ .reg .pred p; setp.ne.u32 p, %4, 0;\n\t"
        "tcgen05.mma.cta_group::1.kind::f16 [%0], %1, %2, %3, {%5,%5,%5,%5}, p; }"
        :: "r"(d), "l"(ad), "l"(bd), "r"(MMA_IDESC), "r"(en), "r"(0u) : "memory");
}
#endif

// ---------------- prep kernels ----------------
__global__ void prep_weights(const float* __restrict__ W_ih, const float* __restrict__ W_hh,
                             const float* __restrict__ b_ih, const float* __restrict__ b_hh,
                             const float* __restrict__ W_out,
                             __half* __restrict__ Bp, float* __restrict__ biasp,
                             float* __restrict__ wihp, float* __restrict__ woutp)
{
    int idx = blockIdx.x * blockDim.x + threadIdx.x;
    if (idx >= NGATE * HDIM) return;
    int np = idx / HDIM, k = idx - np * HDIM;
    int gg = np & 3, j = np >> 2;
    int src = gg * HDIM + j;
    Bp[(size_t)np * HDIM + k] = __float2half_rn(W_hh[(size_t)src * HDIM + k]);
    if (k == 0) { biasp[np] = b_ih[src] + b_hh[src]; wihp[np] = W_ih[src]; }
    if (np == 0) woutp[k] = W_out[k];
}

__global__ void prep_state(const float* __restrict__ hidden, const float* __restrict__ cell,
                           __half* __restrict__ A0, float* __restrict__ cbuf)
{
    int idx = blockIdx.x * blockDim.x + threadIdx.x;
    if (idx >= BSZ * HDIM) return;
    A0[idx] = __float2half_rn(hidden[idx]);
    cbuf[idx] = cell[idx];
}

#if HAS_TCGEN05
// LSTM pointwise for one 32-col chunk in r[32]. Batched reciprocals:
// 4 gate activations share ONE rcp; tanh(c) rcp paired across adjacent j.
__device__ __forceinline__ float epi_math(
    const uint32_t* __restrict__ r, int nbase, int jb, float xb,
    float* __restrict__ cbuf, __half* __restrict__ Aout,
    const float* __restrict__ biasp, const float* __restrict__ wihp,
    const float* __restrict__ woutp, size_t mrow, size_t arow)
{
    const float4 ca  = *(const float4*)(cbuf + mrow + jb);
    const float4 cb2 = *(const float4*)(cbuf + mrow + jb + 4);
    float cold[8] = {ca.x, ca.y, ca.z, ca.w, cb2.x, cb2.y, cb2.z, cb2.w};
    float c2s[8], sos[8];
#pragma unroll
    for (int jl = 0; jl < 8; jl++) {
        const int nn = nbase + jl * 4;
        const float iv = __uint_as_float(r[jl * 4 + 0]) + biasp[nn + 0] + xb * wihp[nn + 0];
        const float fv = __uint_as_float(r[jl * 4 + 1]) + biasp[nn + 1] + xb * wihp[nn + 1];
        const float gv = __uint_as_float(r[jl * 4 + 2]) + biasp[nn + 2] + xb * wihp[nn + 2];
        const float ov = __uint_as_float(r[jl * 4 + 3]) + biasp[nn + 3] + xb * wihp[nn + 3];
        const float ei = __expf(-iv);
        const float ef = __expf(-fv);
        const float eg = __expf(-2.0f * gv);
        const float eo = __expf(-ov);
        const float a = 1.0f + ei, b = 1.0f + ef, cq = 1.0f + eo, d = 1.0f + eg;
        const float ab = a * b, cd = cq * d;
        const float rr = __fdividef(1.0f, ab * cd);     // one RCP for 4 gates
        const float si   = rr * (b * cd);
        const float sf   = rr * (a * cd);
        const float so   = rr * (ab * d);
        const float invd = rr * (ab * cq);
        const float tg = (1.0f - eg) * invd;            // tanh(g)
        c2s[jl] = sf * cold[jl] + si * tg;
        sos[jl] = so;
    }
    union { __half h[8]; uint4 v; } Uhi;
    float psum = 0.0f;
#pragma unroll
    for (int p = 0; p < 4; p++) {
        const float e0 = __expf(-2.0f * c2s[2 * p]);
        const float e1 = __expf(-2.0f * c2s[2 * p + 1]);
        const float q0 = 1.0f + e0, q1 = 1.0f + e1;
        const float rr = __fdividef(1.0f, q0 * q1);     // one RCP for 2 tanh(c)
        const float tc0 = (1.0f - e0) * (rr * q1);
        const float tc1 = (1.0f - e1) * (rr * q0);
        const float hn0 = sos[2 * p] * tc0;
        const float hn1 = sos[2 * p + 1] * tc1;
        Uhi.h[2 * p]     = __float2half_rn(hn0);
        Uhi.h[2 * p + 1] = __float2half_rn(hn1);
        psum = fmaf(hn0, woutp[jb + 2 * p], psum);
        psum = fmaf(hn1, woutp[jb + 2 * p + 1], psum);
    }
    *(float4*)(cbuf + mrow + jb)     = make_float4(c2s[0], c2s[1], c2s[2], c2s[3]);
    *(float4*)(cbuf + mrow + jb + 4) = make_float4(c2s[4], c2s[5], c2s[6], c2s[7]);
    *(uint4*)(Aout + arow + jb) = Uhi.v;
    return psum;
}
#endif

// ---------------- single-wave fused LSTM step (single-term fp16) ----------------
__global__ void __launch_bounds__(NTHREADS, 1)
lstm_step_tma(const __grid_constant__ CUtensorMap tmA,
              const __grid_constant__ CUtensorMap tmB,
              __half* __restrict__ Aout, float* __restrict__ cbuf,
              const float* __restrict__ biasp, const float* __restrict__ wihp,
              const float* __restrict__ woutp,
              const float* __restrict__ partial_prev, float* __restrict__ partial,
              const float* __restrict__ b_out, float* __restrict__ out,
              int t, int use_x)
{
#if HAS_TCGEN05
    extern __shared__ char smem[];
    const uint32_t sbase = smem_u32(smem);
    const int tid = threadIdx.x, wid = tid >> 5, lid = tid & 31;
    const int mx = blockIdx.x & 15, ng = blockIdx.x >> 4;   // 16 m-bands x 8 n-groups
    const int m0 = mx * MT;

    if (tid == 0) {
#pragma unroll
        for (int s = 0; s < NSTAGE; s++) {
            MBARRIER_INIT(sbase + SM_FULL0 + 8 * s, 1);
            MBARRIER_INIT(sbase + SM_EMPTY0 + 8 * s, 1);
        }
        MBARRIER_INIT(sbase + SM_DONE, 1);
    }
    if (wid == 0) TCGEN05_ALLOC(sbase + SM_TMEM, 512);
    __syncthreads();
    uint32_t tmem;
    asm volatile("ld.shared.b32 %0, [%1];" : "=r"(tmem) : "r"(sbase + SM_TMEM));

    if (wid == 0) {
        // ================= MMA warp =================
        TCGEN05_RELINQUISH();
        uint64_t dA[NSTAGE], dB[NSTAGE];
#pragma unroll
        for (int s = 0; s < NSTAGE; s++) {
            const uint32_t aT = sbase + SM_STAGE + s * STAGE_BYTES;
            dA[s] = make_desc_sw64(aT + OFF_A);
            dB[s] = make_desc_sw64(aT + OFF_B);
        }
        int s = 0, ph = 0;
        for (int tile = 0; tile < 2; tile++) {
            asm volatile("bar.sync 1, 288;");          // wait epilogue TMEM drain
            for (int c = 0; c < NCHUNK; c++) {
                MBARRIER_WAIT_PARITY(sbase + SM_FULL0 + 8 * s, ph);
                if (elect1()) {
#pragma unroll
                    for (int kk = 0; kk < 2; kk++) {
                        const uint32_t en0 = (c == 0 && kk == 0) ? 0u : 1u;
                        mma_f16_ss(tmem + 0,   dA[s] + kk * 2,       dB[s] + kk * 2, en0);
                        mma_f16_ss(tmem + 256, dA[s] + 512 + kk * 2, dB[s] + kk * 2, en0);
                    }
                    TCGEN05_COMMIT(sbase + SM_EMPTY0 + 8 * s);
                }
                if (++s == NSTAGE) { s = 0; ph ^= 1; }
            }
            if (elect1()) TCGEN05_COMMIT(sbase + SM_DONE);
        }
    } else if (wid == 1) {
        // ================= TMA producer warp =================
        if (elect1()) {
            int s = 0, ph = 1;
            for (int cc = 0; cc < 2 * NCHUNK; cc++) {
                MBARRIER_WAIT_PARITY(sbase + SM_EMPTY0 + 8 * s, ph);
                const uint32_t sT = sbase + SM_STAGE + s * STAGE_BYTES;
                const uint32_t fb = sbase + SM_FULL0 + 8 * s;
                const int c = cc & (NCHUNK - 1);
                const int n0t = (ng + (cc >> 5) * 8) * NT;
                MBARRIER_EXPECT_TX(fb, STAGE_BYTES);
                tma2d(sT + OFF_A, &tmA, c * 32, m0,  fb);
                tma2d(sT + OFF_B, &tmB, c * 32, n0t, fb);
                if (++s == NSTAGE) { s = 0; ph ^= 1; }
            }
        }
    } else {
        // ================= epilogue warps (w2-9) =================
        const int sp = wid & 3;
        const int half = (wid >= 6) ? 1 : 0;
        const int m = m0 + half * 128 + sp * 32 + lid;
        const size_t mrow = (size_t)m * HDIM;
        const size_t arow = (size_t)m * HDIM;

        asm volatile("bar.arrive 1, 288;");            // pre-arm drain for tile 0

        // feedback pred-reduce (overlaps tile-0 MMA)
        float xb = 0.0f;
        if (use_x) {
            float s = b_out[0];
            const float4* pp = (const float4*)(partial_prev + (size_t)m * JT);
#pragma unroll
            for (int i = 0; i < 4; i++) {
                float4 p = pp[i];
                s += p.x + p.y + p.z + p.w;
            }
            xb = s;
            if (ng == 0) out[(size_t)m * TLEN + (t - 1)] = s;
        }

        const uint32_t dbase = tmem + half * 256;
#pragma unroll 1
        for (int tile = 0; tile < 2; tile++) {
            MBARRIER_WAIT_PARITY(sbase + SM_DONE, tile);
            TCGEN05_FENCE_AFTER();
            const int nt = ng + tile * 8;
            const int n0t = nt * NT, j0t = n0t >> 2;
            float psum = 0.0f;
            uint32_t ra[64], rb[32];
            // pipelined LDTM: all TMEM reads complete BEFORE last 3 math blocks,
            // so the MMA release fires early and tile-1 MMA overlaps the tail.
            TCGEN05_LD_X32(ra,      dbase + 0);
            TCGEN05_LD_X32(ra + 32, dbase + 32);
            TCGEN05_LD_X32(rb,      dbase + 64);
            TCGEN05_WAIT_LD();
            psum += epi_math(ra,      n0t + 0,  j0t + 0, xb, cbuf, Aout, biasp, wihp, woutp, mrow, arow);
            psum += epi_math(ra + 32, n0t + 32, j0t + 8, xb, cbuf, Aout, biasp, wihp, woutp, mrow, arow);
            TCGEN05_LD_X32(ra,      dbase + 96);
            TCGEN05_LD_X32(ra + 32, dbase + 128);
            TCGEN05_WAIT_LD();
            psum += epi_math(rb, n0t + 64, j0t + 16, xb, cbuf, Aout, biasp, wihp, woutp, mrow, arow);
            TCGEN05_LD_X32(rb, dbase + 160);
            TCGEN05_WAIT_LD();
            psum += epi_math(ra,      n0t + 96,  j0t + 24, xb, cbuf, Aout, biasp, wihp, woutp, mrow, arow);
            psum += epi_math(ra + 32, n0t + 128, j0t + 32, xb, cbuf, Aout, biasp, wihp, woutp, mrow, arow);
            TCGEN05_LD_X32(ra,      dbase + 192);
            TCGEN05_LD_X32(ra + 32, dbase + 224);
            TCGEN05_WAIT_LD();
            if (tile == 0) asm volatile("bar.arrive 1, 288;");  // release MMA for tile 1
            psum += epi_math(rb,      n0t + 160, j0t + 40, xb, cbuf, Aout, biasp, wihp, woutp, mrow, arow);
            psum += epi_math(ra,      n0t + 192, j0t + 48, xb, cbuf, Aout, biasp, wihp, woutp, mrow, arow);
            psum += epi_math(ra + 32, n0t + 224, j0t + 56, xb, cbuf, Aout, biasp, wihp, woutp, mrow, arow);
            partial[(size_t)m * JT + nt] = psum;
        }
    }

    __syncthreads();
    if (wid == 0) TCGEN05_DEALLOC(tmem, 512);
#endif
}

// final column (t = TLEN-1) reduce
__global__ void pred_final(const float* __restrict__ partial, const float* __restrict__ b_out,
                           float* __restrict__ out)
{
    const int b = blockIdx.x * blockDim.x + threadIdx.x;
    if (b < BSZ) {
        float s = b_out[0];
        const float* p = partial + (size_t)b * JT;
#pragma unroll
        for (int i = 0; i < JT; i++) s += p[i];
        out[(size_t)b * TLEN + (TLEN - 1)] = s;
    }
}

// ---------------- launch ----------------
typedef CUresult (*PFN_tmEncode)(CUtensorMap*, CUtensorMapDataType, cuuint32_t, void*,
                                 const cuuint64_t*, const cuuint64_t*, const cuuint32_t*,
                                 const cuuint32_t*, CUtensorMapInterleave, CUtensorMapSwizzle,
                                 CUtensorMapL2promotion, CUtensorMapFloatOOBfill);

extern "C" void kernel_launch(void* const* d_in, const int* in_sizes, int n_in,
                              void* d_out, int out_size)
{
    const float* hidden = (const float*)d_in[0];
    const float* cell   = (const float*)d_in[1];
    const float* W_ih   = (const float*)d_in[2];
    const float* W_hh   = (const float*)d_in[3];
    const float* b_ih   = (const float*)d_in[4];
    const float* b_hh   = (const float*)d_in[5];
    const float* W_out  = (const float*)d_in[6];
    const float* b_out  = (const float*)d_in[7];
    float* out = (float*)d_out;

    __half *Abuf, *Bp;
    float *cbuf, *biasp, *wihp, *woutp, *part;
    cudaGetSymbolAddress((void**)&Abuf,  g_A);
    cudaGetSymbolAddress((void**)&Bp,    g_Bp);
    cudaGetSymbolAddress((void**)&cbuf,  g_c);
    cudaGetSymbolAddress((void**)&biasp, g_biasp);
    cudaGetSymbolAddress((void**)&wihp,  g_wihp);
    cudaGetSymbolAddress((void**)&woutp, g_woutp);
    cudaGetSymbolAddress((void**)&part,  g_partial);

    // tensormaps (host encode via driver entry point; no allocation)
    PFN_tmEncode tmEncode = nullptr;
    cudaDriverEntryPointQueryResult qres;
    cudaGetDriverEntryPoint("cuTensorMapEncodeTiled", (void**)&tmEncode,
                            cudaEnableDefault, &qres);
    const size_t NA = (size_t)BSZ * HDIM;
    CUtensorMap tmA0, tmA1, tmB;
    {
        cuuint64_t dimsA[2] = {HDIM, BSZ};
        cuuint64_t strA[1]  = {HDIM * 2};
        cuuint32_t boxA[2]  = {32, 256};
        cuuint32_t est[2]   = {1, 1};
        tmEncode(&tmA0, CU_TENSOR_MAP_DATA_TYPE_FLOAT16, 2, (void*)Abuf,
                 dimsA, strA, boxA, est, CU_TENSOR_MAP_INTERLEAVE_NONE,
                 CU_TENSOR_MAP_SWIZZLE_64B, CU_TENSOR_MAP_L2_PROMOTION_L2_128B,
                 CU_TENSOR_MAP_FLOAT_OOB_FILL_NONE);
        tmEncode(&tmA1, CU_TENSOR_MAP_DATA_TYPE_FLOAT16, 2, (void*)(Abuf + NA),
                 dimsA, strA, boxA, est, CU_TENSOR_MAP_INTERLEAVE_NONE,
                 CU_TENSOR_MAP_SWIZZLE_64B, CU_TENSOR_MAP_L2_PROMOTION_L2_128B,
                 CU_TENSOR_MAP_FLOAT_OOB_FILL_NONE);
        cuuint64_t dimsB[2] = {HDIM, NGATE};
        cuuint64_t strB[1]  = {HDIM * 2};
        cuuint32_t boxB[2]  = {32, 256};
        tmEncode(&tmB, CU_TENSOR_MAP_DATA_TYPE_FLOAT16, 2, (void*)Bp,
                 dimsB, strB, boxB, est, CU_TENSOR_MAP_INTERLEAVE_NONE,
                 CU_TENSOR_MAP_SWIZZLE_64B, CU_TENSOR_MAP_L2_PROMOTION_L2_128B,
                 CU_TENSOR_MAP_FLOAT_OOB_FILL_NONE);
    }

    cudaFuncSetAttribute(lstm_step_tma, cudaFuncAttributeMaxDynamicSharedMemorySize, DSMEM);

    prep_weights<<<(NGATE * HDIM + 255) / 256, 256>>>(W_ih, W_hh, b_ih, b_hh, W_out,
                                                      Bp, biasp, wihp, woutp);
    prep_state<<<(BSZ * HDIM + 255) / 256, 256>>>(hidden, cell, Abuf, cbuf);

    const size_t NP = (size_t)BSZ * JT;
    for (int t = 0; t < TLEN; t++) {
        __half* Aout = Abuf + (size_t)((t + 1) & 1) * NA;
        const float* ppart = part + (size_t)((t + 1) & 1) * NP;   // (t-1)&1 == (t+1)&1
        float* cpart = part + (size_t)(t & 1) * NP;
        lstm_step_tma<<<128, NTHREADS, DSMEM>>>((t & 1) ? tmA1 : tmA0, tmB,
                                                Aout, cbuf, biasp, wihp, woutp,
                                                ppart, cpart, b_out, out,
                                                t, (t > 0) ? 1 : 0);
    }
    pred_final<<<BSZ / 256, 256>>>(part + (size_t)((TLEN - 1) & 1) * NP, b_out, out);
}

// round 10
// speedup vs baseline: 2.2102x; 1.0972x over previous
#include <cuda_runtime.h>
#include <cuda.h>
#include <cuda_fp16.h>
#include <math.h>
#include <stdint.h>

// ---------------- problem constants ----------------
#define HDIM  1024
#define BSZ   4096
#define TLEN  128
#define NGATE 4096            // 4 gates x HDIM, interleaved n' = j*4 + g
#define MT    256
#define NT    256
#define KC    64              // K chunk (elems) = 128B rows, SW128
#define NCHUNK 16             // per n-tile
#define NSTAGE 3
#define JT    16
#define NTHREADS 320          // w0 MMA, w1 TMA, w2-9 epilogue

#if defined(__CUDA_ARCH__) && (defined(__CUDA_ARCH_FEAT_SM103_ALL) || defined(__CUDA_ARCH_FEAT_SM100_ALL) || defined(__CUDA_ARCH_FEAT_SM101_ALL))
#define HAS_TCGEN05 1
#else
#define HAS_TCGEN05 0
#endif

// ---------------- persistent device state ----------------
__device__ __align__(1024) __half g_A[2][(size_t)BSZ * HDIM];  // h fp16 (ping-pong)
__device__ __align__(1024) __half g_Bp[(size_t)NGATE * HDIM];  // weights fp16, gate-interleaved
__device__ float g_c[(size_t)BSZ * HDIM];
__device__ float g_biasp[NGATE];
__device__ float g_wihp[NGATE];
__device__ float g_woutp[HDIM];
__device__ float g_partial[2][(size_t)BSZ * JT];               // double-buffered

// ---------------- smem layout ----------------
#define SM_TMEM   0
#define SM_FULL0  64
#define SM_EMPTY0 (SM_FULL0 + 8*NSTAGE)
#define SM_DONE   (SM_EMPTY0 + 8*NSTAGE)
#define SM_STAGE  1024
#define STAGE_BYTES 65536       // A 32K | B 32K
#define OFF_A 0
#define OFF_B 32768
#define DSMEM (SM_STAGE + NSTAGE*STAGE_BYTES)

// idesc: F32 accum, F16 a/b, N=256, M=128
#define MMA_IDESC 0x08400010u

// ---------------- arch-neutral helpers ----------------
__device__ __forceinline__ uint32_t smem_u32(const void* p) {
    uint32_t a;
    asm("{ .reg .u64 t; cvta.to.shared.u64 t, %1; cvt.u32.u64 %0, t; }" : "=r"(a) : "l"(p));
    return a;
}
__device__ __forceinline__ uint32_t elect1() {
    uint32_t r;
    asm volatile("{ .reg .pred p; elect.sync _|p, 0xFFFFFFFF; selp.b32 %0, 1, 0, p; }" : "=r"(r));
    return r;
}
#define MBARRIER_INIT(addr, cnt) \
    asm volatile("mbarrier.init.shared.b64 [%0], %1;" :: "r"((uint32_t)(addr)), "r"((uint32_t)(cnt)) : "memory")
#define MBARRIER_EXPECT_TX(addr, bytes) \
    asm volatile("mbarrier.arrive.expect_tx.shared.b64 _, [%0], %1;" :: "r"((uint32_t)(addr)), "r"((uint32_t)(bytes)) : "memory")
#define MBARRIER_WAIT_PARITY(addr, par) do { \
    uint32_t _m = (uint32_t)(addr); uint32_t _p = (uint32_t)(par); uint32_t _d; \
    asm volatile("{ .reg .pred p; mbarrier.try_wait.parity.acquire.cta.shared::cta.b64 p, [%1], %2; selp.b32 %0,1,0,p; }" \
        : "=r"(_d) : "r"(_m), "r"(_p) : "memory"); \
    if (!_d) { \
        asm volatile("{ .reg .pred P1; WL_%=: mbarrier.try_wait.parity.acquire.cta.shared::cta.b64 P1, [%0], %1, 0x989680; @P1 bra.uni WD_%=; bra.uni WL_%=; WD_%=: }" \
            :: "r"(_m), "r"(_p) : "memory"); \
    } } while (0)
__device__ __forceinline__ void tma2d(uint32_t dst, const void* tmap, int x, int y, uint32_t mbar) {
    asm volatile("cp.async.bulk.tensor.2d.shared::cta.global.tile.mbarrier::complete_tx::bytes "
                 "[%0], [%1, {%2, %3}], [%4];"
                 :: "r"(dst), "l"(tmap), "r"(x), "r"(y), "r"(mbar) : "memory");
}

// SW128 K-major smem descriptor: layout 2, version 1, SBO=64, LBO=1
static __device__ __forceinline__ uint64_t make_desc_sw128(uint32_t addr) {
    const uint64_t base = (uint64_t(2) << 61) | (uint64_t(1) << 46) | (uint64_t(64) << 32) | (uint64_t(1) << 16);
    return base | ((uint64_t)(addr >> 4) & 0x3FFF);
}

// ---------------- tcgen05 (sm_103a-only PTX pass) ----------------
#if HAS_TCGEN05
#define TCGEN05_ALLOC(sa, n) \
    asm volatile("tcgen05.alloc.cta_group::1.sync.aligned.shared::cta.b32 [%0], %1;" :: "r"((uint32_t)(sa)), "r"((uint32_t)(n)) : "memory")
#define TCGEN05_DEALLOC(t, n) \
    asm volatile("tcgen05.dealloc.cta_group::1.sync.aligned.b32 %0, %1;" :: "r"(t), "r"((uint32_t)(n)))
#define TCGEN05_RELINQUISH() \
    asm volatile("tcgen05.relinquish_alloc_permit.cta_group::1.sync.aligned;")
#define TCGEN05_COMMIT(mb) \
    asm volatile("tcgen05.commit.cta_group::1.mbarrier::arrive::one.shared::cluster.b64 [%0];" :: "r"((uint32_t)(mb)) : "memory")
#define TCGEN05_FENCE_AFTER()  asm volatile("tcgen05.fence::after_thread_sync;" ::: "memory")
#define TCGEN05_WAIT_LD()      asm volatile("tcgen05.wait::ld.sync.aligned;" ::: "memory")

#define TCGEN05_LD_X32(r, ta) \
    asm volatile("tcgen05.ld.sync.aligned.32x32b.x32.b32 " \
        "{%0,%1,%2,%3,%4,%5,%6,%7,%8,%9,%10,%11,%12,%13,%14,%15," \
        "%16,%17,%18,%19,%20,%21,%22,%23,%24,%25,%26,%27,%28,%29,%30,%31}, [%32];" \
        : "=r"((r)[0]),"=r"((r)[1]),"=r"((r)[2]),"=r"((r)[3]),"=r"((r)[4]),"=r"((r)[5]),"=r"((r)[6]),"=r"((r)[7]), \
          "=r"((r)[8]),"=r"((r)[9]),"=r"((r)[10]),"=r"((r)[11]),"=r"((r)[12]),"=r"((r)[13]),"=r"((r)[14]),"=r"((r)[15]), \
          "=r"((r)[16]),"=r"((r)[17]),"=r"((r)[18]),"=r"((r)[19]),"=r"((r)[20]),"=r"((r)[21]),"=r"((r)[22]),"=r"((r)[23]), \
          "=r"((r)[24]),"=r"((r)[25]),"=r"((r)[26]),"=r"((r)[27]),"=r"((r)[28]),"=r"((r)[29]),"=r"((r)[30]),"=r"((r)[31]) \
        : "r"(ta))

__device__ __forceinline__ void mma_f16_ss(uint32_t d, uint64_t ad, uint64_t bd, uint32_t en) {
    asm volatile(
        "{ .reg .pred p; setp.ne.u32 p, %4, 0;\n\t"
        "tcgen05.mma.cta_group::1.kind::f16 [%0], %1, %2, %3, {%5,%5,%5,%5}, p; }"
        :: "r"(d), "l"(ad), "l"(bd), "r"(MMA_IDESC), "r"(en), "r"(0u) : "memory");
}
#endif

// ---------------- prep kernels ----------------
__global__ void prep_weights(const float* __restrict__ W_ih, const float* __restrict__ W_hh,
                             const float* __restrict__ b_ih, const float* __restrict__ b_hh,
                             const float* __restrict__ W_out,
                             __half* __restrict__ Bp, float* __restrict__ biasp,
                             float* __restrict__ wihp, float* __restrict__ woutp)
{
    int idx = blockIdx.x * blockDim.x + threadIdx.x;
    if (idx >= NGATE * HDIM) return;
    int np = idx / HDIM, k = idx - np * HDIM;
    int gg = np & 3, j = np >> 2;
    int src = gg * HDIM + j;
    Bp[(size_t)np * HDIM + k] = __float2half_rn(W_hh[(size_t)src * HDIM + k]);
    if (k == 0) { biasp[np] = b_ih[src] + b_hh[src]; wihp[np] = W_ih[src]; }
    if (np == 0) woutp[k] = W_out[k];
}

__global__ void prep_state(const float* __restrict__ hidden, const float* __restrict__ cell,
                           __half* __restrict__ A0, float* __restrict__ cbuf)
{
    int idx = blockIdx.x * blockDim.x + threadIdx.x;
    if (idx >= BSZ * HDIM) return;
    A0[idx] = __float2half_rn(hidden[idx]);
    cbuf[idx] = cell[idx];
}

#if HAS_TCGEN05
// LSTM pointwise for one 32-col chunk in r[32]. Batched reciprocals:
// 4 gate activations share ONE rcp; tanh(c) rcp paired across adjacent j.
__device__ __forceinline__ float epi_math(
    const uint32_t* __restrict__ r, int nbase, int jb, float xb,
    float* __restrict__ cbuf, __half* __restrict__ Aout,
    const float* __restrict__ biasp, const float* __restrict__ wihp,
    const float* __restrict__ woutp, size_t mrow, size_t arow)
{
    const float4 ca  = *(const float4*)(cbuf + mrow + jb);
    const float4 cb2 = *(const float4*)(cbuf + mrow + jb + 4);
    float cold[8] = {ca.x, ca.y, ca.z, ca.w, cb2.x, cb2.y, cb2.z, cb2.w};
    float c2s[8], sos[8];
#pragma unroll
    for (int jl = 0; jl < 8; jl++) {
        const int nn = nbase + jl * 4;
        const float iv = __uint_as_float(r[jl * 4 + 0]) + biasp[nn + 0] + xb * wihp[nn + 0];
        const float fv = __uint_as_float(r[jl * 4 + 1]) + biasp[nn + 1] + xb * wihp[nn + 1];
        const float gv = __uint_as_float(r[jl * 4 + 2]) + biasp[nn + 2] + xb * wihp[nn + 2];
        const float ov = __uint_as_float(r[jl * 4 + 3]) + biasp[nn + 3] + xb * wihp[nn + 3];
        const float ei = __expf(-iv);
        const float ef = __expf(-fv);
        const float eg = __expf(-2.0f * gv);
        const float eo = __expf(-ov);
        const float a = 1.0f + ei, b = 1.0f + ef, cq = 1.0f + eo, d = 1.0f + eg;
        const float ab = a * b, cd = cq * d;
        const float rr = __fdividef(1.0f, ab * cd);     // one RCP for 4 gates
        const float si   = rr * (b * cd);
        const float sf   = rr * (a * cd);
        const float so   = rr * (ab * d);
        const float invd = rr * (ab * cq);
        const float tg = (1.0f - eg) * invd;            // tanh(g)
        c2s[jl] = sf * cold[jl] + si * tg;
        sos[jl] = so;
    }
    union { __half h[8]; uint4 v; } Uhi;
    float psum = 0.0f;
#pragma unroll
    for (int p = 0; p < 4; p++) {
        const float e0 = __expf(-2.0f * c2s[2 * p]);
        const float e1 = __expf(-2.0f * c2s[2 * p + 1]);
        const float q0 = 1.0f + e0, q1 = 1.0f + e1;
        const float rr = __fdividef(1.0f, q0 * q1);     // one RCP for 2 tanh(c)
        const float tc0 = (1.0f - e0) * (rr * q1);
        const float tc1 = (1.0f - e1) * (rr * q0);
        const float hn0 = sos[2 * p] * tc0;
        const float hn1 = sos[2 * p + 1] * tc1;
        Uhi.h[2 * p]     = __float2half_rn(hn0);
        Uhi.h[2 * p + 1] = __float2half_rn(hn1);
        psum = fmaf(hn0, woutp[jb + 2 * p], psum);
        psum = fmaf(hn1, woutp[jb + 2 * p + 1], psum);
    }
    *(float4*)(cbuf + mrow + jb)     = make_float4(c2s[0], c2s[1], c2s[2], c2s[3]);
    *(float4*)(cbuf + mrow + jb + 4) = make_float4(c2s[4], c2s[5], c2s[6], c2s[7]);
    *(uint4*)(Aout + arow + jb) = Uhi.v;
    return psum;
}
#endif

// ---------------- single-wave fused LSTM step (KC=64 chunks) ----------------
__global__ void __launch_bounds__(NTHREADS, 1)
lstm_step_tma(const __grid_constant__ CUtensorMap tmA,
              const __grid_constant__ CUtensorMap tmB,
              __half* __restrict__ Aout, float* __restrict__ cbuf,
              const float* __restrict__ biasp, const float* __restrict__ wihp,
              const float* __restrict__ woutp,
              const float* __restrict__ partial_prev, float* __restrict__ partial,
              const float* __restrict__ b_out, float* __restrict__ out,
              int t, int use_x)
{
#if HAS_TCGEN05
    extern __shared__ char smem[];
    const uint32_t sbase = smem_u32(smem);
    const int tid = threadIdx.x, wid = tid >> 5, lid = tid & 31;
    const int mx = blockIdx.x & 15, ng = blockIdx.x >> 4;   // 16 m-bands x 8 n-groups
    const int m0 = mx * MT;

    if (tid == 0) {
#pragma unroll
        for (int s = 0; s < NSTAGE; s++) {
            MBARRIER_INIT(sbase + SM_FULL0 + 8 * s, 1);
            MBARRIER_INIT(sbase + SM_EMPTY0 + 8 * s, 1);
        }
        MBARRIER_INIT(sbase + SM_DONE, 1);
    }
    if (wid == 0) TCGEN05_ALLOC(sbase + SM_TMEM, 512);
    __syncthreads();
    uint32_t tmem;
    asm volatile("ld.shared.b32 %0, [%1];" : "=r"(tmem) : "r"(sbase + SM_TMEM));

    if (wid == 0) {
        // ================= MMA warp =================
        TCGEN05_RELINQUISH();
        uint64_t dA[NSTAGE], dB[NSTAGE];
#pragma unroll
        for (int s = 0; s < NSTAGE; s++) {
            const uint32_t aT = sbase + SM_STAGE + s * STAGE_BYTES;
            dA[s] = make_desc_sw128(aT + OFF_A);
            dB[s] = make_desc_sw128(aT + OFF_B);
        }
        int s = 0, ph = 0;
        for (int tile = 0; tile < 2; tile++) {
            asm volatile("bar.sync 1, 288;");          // wait epilogue TMEM drain
            for (int c = 0; c < NCHUNK; c++) {
                MBARRIER_WAIT_PARITY(sbase + SM_FULL0 + 8 * s, ph);
                if (elect1()) {
#pragma unroll
                    for (int kk = 0; kk < 4; kk++) {
                        const uint32_t en0 = (c == 0 && kk == 0) ? 0u : 1u;
                        // rows 128..255 of A tile: +128 rows * 128B = 16KB = 1024 desc units
                        mma_f16_ss(tmem + 0,   dA[s] + kk * 2,        dB[s] + kk * 2, en0);
                        mma_f16_ss(tmem + 256, dA[s] + 1024 + kk * 2, dB[s] + kk * 2, en0);
                    }
                    TCGEN05_COMMIT(sbase + SM_EMPTY0 + 8 * s);
                }
                if (++s == NSTAGE) { s = 0; ph ^= 1; }
            }
            if (elect1()) TCGEN05_COMMIT(sbase + SM_DONE);
        }
    } else if (wid == 1) {
        // ================= TMA producer warp =================
        if (elect1()) {
            int s = 0, ph = 1;
            for (int cc = 0; cc < 2 * NCHUNK; cc++) {
                MBARRIER_WAIT_PARITY(sbase + SM_EMPTY0 + 8 * s, ph);
                const uint32_t sT = sbase + SM_STAGE + s * STAGE_BYTES;
                const uint32_t fb = sbase + SM_FULL0 + 8 * s;
                const int c = cc & (NCHUNK - 1);
                const int n0t = (ng + (cc >> 4) * 8) * NT;
                MBARRIER_EXPECT_TX(fb, STAGE_BYTES);
                tma2d(sT + OFF_A, &tmA, c * KC, m0,  fb);
                tma2d(sT + OFF_B, &tmB, c * KC, n0t, fb);
                if (++s == NSTAGE) { s = 0; ph ^= 1; }
            }
        }
    } else {
        // ================= epilogue warps (w2-9) =================
        const int sp = wid & 3;
        const int half = (wid >= 6) ? 1 : 0;
        const int m = m0 + half * 128 + sp * 32 + lid;
        const size_t mrow = (size_t)m * HDIM;
        const size_t arow = (size_t)m * HDIM;

        asm volatile("bar.arrive 1, 288;");            // pre-arm drain for tile 0

        // feedback pred-reduce (overlaps tile-0 MMA)
        float xb = 0.0f;
        if (use_x) {
            float s = b_out[0];
            const float4* pp = (const float4*)(partial_prev + (size_t)m * JT);
#pragma unroll
            for (int i = 0; i < 4; i++) {
                float4 p = pp[i];
                s += p.x + p.y + p.z + p.w;
            }
            xb = s;
            if (ng == 0) out[(size_t)m * TLEN + (t - 1)] = s;
        }

        const uint32_t dbase = tmem + half * 256;
#pragma unroll 1
        for (int tile = 0; tile < 2; tile++) {
            MBARRIER_WAIT_PARITY(sbase + SM_DONE, tile);
            TCGEN05_FENCE_AFTER();
            const int nt = ng + tile * 8;
            const int n0t = nt * NT, j0t = n0t >> 2;
            float psum = 0.0f;
            uint32_t ra[64], rb[32];
            // pipelined LDTM: all TMEM reads complete BEFORE last 3 math blocks,
            // so the MMA release fires early and tile-1 MMA overlaps the tail.
            TCGEN05_LD_X32(ra,      dbase + 0);
            TCGEN05_LD_X32(ra + 32, dbase + 32);
            TCGEN05_LD_X32(rb,      dbase + 64);
            TCGEN05_WAIT_LD();
            psum += epi_math(ra,      n0t + 0,  j0t + 0, xb, cbuf, Aout, biasp, wihp, woutp, mrow, arow);
            psum += epi_math(ra + 32, n0t + 32, j0t + 8, xb, cbuf, Aout, biasp, wihp, woutp, mrow, arow);
            TCGEN05_LD_X32(ra,      dbase + 96);
            TCGEN05_LD_X32(ra + 32, dbase + 128);
            TCGEN05_WAIT_LD();
            psum += epi_math(rb, n0t + 64, j0t + 16, xb, cbuf, Aout, biasp, wihp, woutp, mrow, arow);
            TCGEN05_LD_X32(rb, dbase + 160);
            TCGEN05_WAIT_LD();
            psum += epi_math(ra,      n0t + 96,  j0t + 24, xb, cbuf, Aout, biasp, wihp, woutp, mrow, arow);
            psum += epi_math(ra + 32, n0t + 128, j0t + 32, xb, cbuf, Aout, biasp, wihp, woutp, mrow, arow);
            TCGEN05_LD_X32(ra,      dbase + 192);
            TCGEN05_LD_X32(ra + 32, dbase + 224);
            TCGEN05_WAIT_LD();
            if (tile == 0) asm volatile("bar.arrive 1, 288;");  // release MMA for tile 1
            psum += epi_math(rb,      n0t + 160, j0t + 40, xb, cbuf, Aout, biasp, wihp, woutp, mrow, arow);
            psum += epi_math(ra,      n0t + 192, j0t + 48, xb, cbuf, Aout, biasp, wihp, woutp, mrow, arow);
            psum += epi_math(ra + 32, n0t + 224, j0t + 56, xb, cbuf, Aout, biasp, wihp, woutp, mrow, arow);
            partial[(size_t)m * JT + nt] = psum;
        }
    }

    __syncthreads();
    if (wid == 0) TCGEN05_DEALLOC(tmem, 512);
#endif
}

// final column (t = TLEN-1) reduce
__global__ void pred_final(const float* __restrict__ partial, const float* __restrict__ b_out,
                           float* __restrict__ out)
{
    const int b = blockIdx.x * blockDim.x + threadIdx.x;
    if (b < BSZ) {
        float s = b_out[0];
        const float* p = partial + (size_t)b * JT;
#pragma unroll
        for (int i = 0; i < JT; i++) s += p[i];
        out[(size_t)b * TLEN + (TLEN - 1)] = s;
    }
}

// ---------------- launch ----------------
typedef CUresult (*PFN_tmEncode)(CUtensorMap*, CUtensorMapDataType, cuuint32_t, void*,
                                 const cuuint64_t*, const cuuint64_t*, const cuuint32_t*,
                                 const cuuint32_t*, CUtensorMapInterleave, CUtensorMapSwizzle,
                                 CUtensorMapL2promotion, CUtensorMapFloatOOBfill);

extern "C" void kernel_launch(void* const* d_in, const int* in_sizes, int n_in,
                              void* d_out, int out_size)
{
    const float* hidden = (const float*)d_in[0];
    const float* cell   = (const float*)d_in[1];
    const float* W_ih   = (const float*)d_in[2];
    const float* W_hh   = (const float*)d_in[3];
    const float* b_ih   = (const float*)d_in[4];
    const float* b_hh   = (const float*)d_in[5];
    const float* W_out  = (const float*)d_in[6];
    const float* b_out  = (const float*)d_in[7];
    float* out = (float*)d_out;

    __half *Abuf, *Bp;
    float *cbuf, *biasp, *wihp, *woutp, *part;
    cudaGetSymbolAddress((void**)&Abuf,  g_A);
    cudaGetSymbolAddress((void**)&Bp,    g_Bp);
    cudaGetSymbolAddress((void**)&cbuf,  g_c);
    cudaGetSymbolAddress((void**)&biasp, g_biasp);
    cudaGetSymbolAddress((void**)&wihp,  g_wihp);
    cudaGetSymbolAddress((void**)&woutp, g_woutp);
    cudaGetSymbolAddress((void**)&part,  g_partial);

    // tensormaps (host encode via driver entry point; no allocation)
    PFN_tmEncode tmEncode = nullptr;
    cudaDriverEntryPointQueryResult qres;
    cudaGetDriverEntryPoint("cuTensorMapEncodeTiled", (void**)&tmEncode,
                            cudaEnableDefault, &qres);
    const size_t NA = (size_t)BSZ * HDIM;
    CUtensorMap tmA0, tmA1, tmB;
    {
        cuuint64_t dimsA[2] = {HDIM, BSZ};
        cuuint64_t strA[1]  = {HDIM * 2};
        cuuint32_t boxA[2]  = {KC, 256};
        cuuint32_t est[2]   = {1, 1};
        tmEncode(&tmA0, CU_TENSOR_MAP_DATA_TYPE_FLOAT16, 2, (void*)Abuf,
                 dimsA, strA, boxA, est, CU_TENSOR_MAP_INTERLEAVE_NONE,
                 CU_TENSOR_MAP_SWIZZLE_128B, CU_TENSOR_MAP_L2_PROMOTION_L2_128B,
                 CU_TENSOR_MAP_FLOAT_OOB_FILL_NONE);
        tmEncode(&tmA1, CU_TENSOR_MAP_DATA_TYPE_FLOAT16, 2, (void*)(Abuf + NA),
                 dimsA, strA, boxA, est, CU_TENSOR_MAP_INTERLEAVE_NONE,
                 CU_TENSOR_MAP_SWIZZLE_128B, CU_TENSOR_MAP_L2_PROMOTION_L2_128B,
                 CU_TENSOR_MAP_FLOAT_OOB_FILL_NONE);
        cuuint64_t dimsB[2] = {HDIM, NGATE};
        cuuint64_t strB[1]  = {HDIM * 2};
        cuuint32_t boxB[2]  = {KC, 256};
        tmEncode(&tmB, CU_TENSOR_MAP_DATA_TYPE_FLOAT16, 2, (void*)Bp,
                 dimsB, strB, boxB, est, CU_TENSOR_MAP_INTERLEAVE_NONE,
                 CU_TENSOR_MAP_SWIZZLE_128B, CU_TENSOR_MAP_L2_PROMOTION_L2_128B,
                 CU_TENSOR_MAP_FLOAT_OOB_FILL_NONE);
    }

    cudaFuncSetAttribute(lstm_step_tma, cudaFuncAttributeMaxDynamicSharedMemorySize, DSMEM);

    prep_weights<<<(NGATE * HDIM + 255) / 256, 256>>>(W_ih, W_hh, b_ih, b_hh, W_out,
                                                      Bp, biasp, wihp, woutp);
    prep_state<<<(BSZ * HDIM + 255) / 256, 256>>>(hidden, cell, Abuf, cbuf);

    const size_t NP = (size_t)BSZ * JT;
    for (int t = 0; t < TLEN; t++) {
        __half* Aout = Abuf + (size_t)((t + 1) & 1) * NA;
        const float* ppart = part + (size_t)((t + 1) & 1) * NP;   // (t-1)&1 == (t+1)&1
        float* cpart = part + (size_t)(t & 1) * NP;
        lstm_step_tma<<<128, NTHREADS, DSMEM>>>((t & 1) ? tmA1 : tmA0, tmB,
                                                Aout, cbuf, biasp, wihp, woutp,
                                                ppart, cpart, b_out, out,
                                                t, (t > 0) ? 1 : 0);
    }
    pred_final<<<BSZ / 256, 256>>>(part + (size_t)((TLEN - 1) & 1) * NP, b_out, out);
}